// round 15
// baseline (speedup 1.0000x reference)
#include <cuda_runtime.h>
#include <cuda_fp16.h>
#include <math.h>
#include <stdint.h>

#define BATCH 2
#define SEQ   2048
#define DIM   1024
#define NH    16
#define HD    64
#define NBLK  32
#define BS    64
#define MROWS (BATCH * SEQ)        // 4096
#define KTOT  1024
#define KCH   64
#define NCHUNK (KTOT / KCH)        // 16
#define TM    128
#define TN    128
#define RSB   144                  // GEMM tile row stride bytes
#define STAGE 18432                // 128 rows * 144B
#define STAGE_H 9216
#define SM_TOTAL (6 * STAGE + 32)

// attention tiles
#define ARS   272                  // K tile rows: 256B data + 16 pad
#define ATILE 17408
#define ATILE_H 8704
#define VRS   144                  // V tile rows: 128B data + 16 pad
#define VTILE 9216
#define VTILE_H 4608
// smem: K0 @0, K1 @ATILE, V0 @2*ATILE, V1 @2*ATILE+VTILE, mbars after
#define ASM_TOTAL (2 * ATILE + 2 * VTILE + 32)   // 53280

// ---------------- device scratch (tiled, pre-padded layouts) ----------------
__device__ __half g_Xc[(size_t)32 * 16 * STAGE_H];
__device__ __half g_Oc[(size_t)32 * 16 * STAGE_H];
__device__ __half g_Wqkv[(size_t)24 * 16 * STAGE_H];
__device__ __half g_Wo[(size_t)8 * 16 * STAGE_H];
__device__ __half g_Qa[(size_t)32 * NBLK * ATILE_H];      // [bh][qb] 64x136h [hi|lo]
__device__ __half g_Ka[(size_t)32 * NBLK * ATILE_H];      // [bh][kb] [hi|hi]
__device__ __half g_Va[(size_t)32 * NBLK * VTILE_H];      // [bh][kb] Vt[d][j] hi, 72h rows
__device__ unsigned char g_bm[NBLK * NBLK];

// ---------------- helpers ----------------
__device__ __forceinline__ uint32_t smem_u32(const void* p) {
    uint32_t a;
    asm("{ .reg .u64 t; cvta.to.shared.u64 t, %1; cvt.u32.u64 %0, t; }" : "=r"(a) : "l"(p));
    return a;
}
#define LDSM_X4(r0, r1, r2, r3, addr) \
    asm volatile("ldmatrix.sync.aligned.m8n8.x4.shared.b16 {%0,%1,%2,%3}, [%4];" \
        : "=r"(r0), "=r"(r1), "=r"(r2), "=r"(r3) : "r"(addr))

#define MBAR_INIT(a, c) \
    asm volatile("mbarrier.init.shared.b64 [%0], %1;" :: "r"(a), "r"(c) : "memory")
#define MBAR_EXPECT(a, n) \
    asm volatile("mbarrier.arrive.expect_tx.shared.b64 _, [%0], %1;" :: "r"(a), "r"(n) : "memory")
#define BULKCP(dst, src, n, mb) \
    asm volatile("cp.async.bulk.shared::cluster.global.mbarrier::complete_tx::bytes [%0], [%1], %2, [%3];" \
        :: "r"(dst), "l"(src), "r"(n), "r"(mb) : "memory")
#define MBAR_WAIT(addr, par) do { \
    uint32_t _m = (addr), _p = (par), _d; \
    asm volatile("{ .reg .pred p; mbarrier.try_wait.parity.acquire.cta.shared::cta.b64 p, [%1], %2; selp.b32 %0,1,0,p; }" \
        : "=r"(_d) : "r"(_m), "r"(_p) : "memory"); \
    if (!_d) { \
        asm volatile("{ .reg .pred P; L1_%=: mbarrier.try_wait.parity.acquire.cta.shared::cta.b64 P, [%0], %1, 0x989680; @P bra.uni L2_%=; bra.uni L1_%=; L2_%=: }" \
            :: "r"(_m), "r"(_p) : "memory"); \
    } } while (0)

__device__ __forceinline__ void mma16816(float* c, const uint32_t* a, uint32_t b0, uint32_t b1) {
    asm volatile("mma.sync.aligned.m16n8k16.row.col.f32.f16.f16.f32 "
        "{%0,%1,%2,%3}, {%4,%5,%6,%7}, {%8,%9}, {%0,%1,%2,%3};"
        : "+f"(c[0]), "+f"(c[1]), "+f"(c[2]), "+f"(c[3])
        : "r"(a[0]), "r"(a[1]), "r"(a[2]), "r"(a[3]), "r"(b0), "r"(b1));
}
__device__ __forceinline__ void split2h(float x, __half& h, __half& l) {
    h = __float2half_rn(x);
    l = __float2half_rn(x - __half2float(h));
}
__device__ __forceinline__ uint32_t pack2h(__half a, __half b) {
    return (uint32_t)__half_as_ushort(a) | ((uint32_t)__half_as_ushort(b) << 16);
}

// ---------------- mask build (dtype-agnostic) ----------------
__global__ void build_block_mask(const unsigned char* __restrict__ m)
{
    const unsigned char b1 = m[1];
    int esz = (b1 == 0) ? 4 : (b1 == 1 ? 1 : 2);
    int idx = blockIdx.x * blockDim.x + threadIdx.x;
    if (idx >= NBLK * NBLK) return;
    int qb = idx / NBLK, kb = idx % NBLK;
    size_t elem = (size_t)(qb * BS) * SEQ + (size_t)kb * BS;
    bool allowed;
    if (esz == 1)      allowed = m[elem] != 0;
    else if (esz == 2) allowed = ((const unsigned short*)m)[elem] != 0;
    else               allowed = ((const unsigned int*)m)[elem] != 0;
    g_bm[idx] = allowed ? 1 : 0;
}

// ---------------- fp32 -> fp16 conversions into tiled layouts ----------------
__global__ void conv_act(const float* __restrict__ X, __half* __restrict__ out, int rows)
{
    int i = blockIdx.x * blockDim.x + threadIdx.x;
    if (i >= rows * DIM) return;
    int row = i >> 10, col = i & 1023;
    size_t idx = ((size_t)((row >> 7) * 16 + (col >> 6))) * STAGE_H
               + (row & 127) * 72 + (col & 63);
    out[idx] = __float2half_rn(X[i]);
}
__global__ void conv_wgt_all(const float* __restrict__ Wq, const float* __restrict__ Wk,
                             const float* __restrict__ Wv, const float* __restrict__ Wo,
                             __half* __restrict__ Wqkv, __half* __restrict__ Woc)
{
    int i = blockIdx.x * blockDim.x + threadIdx.x;
    if (i >= 4 * DIM * DIM) return;
    int w = i >> 20;
    int j = i & (DIM * DIM - 1);
    const float* W = (w == 0) ? Wq : (w == 1) ? Wk : (w == 2) ? Wv : Wo;
    int r = j >> 10, c = j & 1023;
    __half h = __float2half_rn(W[j]);
    if (w < 3) {
        int grow = w * 1024 + r;
        size_t idx = ((size_t)((grow >> 7) * 16 + (c >> 6))) * STAGE_H
                   + (grow & 127) * 72 + (c & 63);
        Wqkv[idx] = h;
    } else {
        size_t idx = ((size_t)((r >> 7) * 16 + (c >> 6))) * STAGE_H
                   + (r & 127) * 72 + (c & 63);
        Woc[idx] = h;
    }
}

// ---------------- bulk-copy pipelined mma.sync GEMM (8 warps, 64x32) ----------------
template<bool QKV>
__global__ void __launch_bounds__(256, 2)
gemm_mma(const __half* __restrict__ A, const __half* __restrict__ Bw,
         __half* __restrict__ Qa, __half* __restrict__ Ka,
         __half* __restrict__ Va, float* __restrict__ C)
{
    extern __shared__ char dsm[];
    const uint32_t sb = smem_u32(dsm);
    const int tid = threadIdx.x;
    const int wid = tid >> 5, l = tid & 31;
    const int wm = wid >> 2, wn = wid & 3;
    const int m0 = blockIdx.y * TM, n0 = blockIdx.x * TN;

    const uint32_t mbb = sb + 6 * STAGE;
    if (tid == 0) {
        MBAR_INIT(mbb, 1); MBAR_INIT(mbb + 8, 1); MBAR_INIT(mbb + 16, 1);
    }
    __syncthreads();

    const char* Asrc = (const char*)A + (size_t)blockIdx.y * 16 * STAGE;
    const char* Bsrc = (const char*)Bw + (size_t)blockIdx.x * 16 * STAGE;

    if (tid == 0) {
#pragma unroll
        for (int s = 0; s < 2; s++) {
            MBAR_EXPECT(mbb + 8 * s, 2 * STAGE);
            BULKCP(sb + s * STAGE, Asrc + (size_t)s * STAGE, STAGE, mbb + 8 * s);
            BULKCP(sb + (3 + s) * STAGE, Bsrc + (size_t)s * STAGE, STAGE, mbb + 8 * s);
        }
    }

    float acc[4][4][4];
#pragma unroll
    for (int i = 0; i < 4; i++)
#pragma unroll
        for (int j = 0; j < 4; j++)
#pragma unroll
            for (int q = 0; q < 4; q++) acc[i][j][q] = 0.f;

    const uint32_t a_off = (uint32_t)((l & 15) * RSB + (l >> 4) * 16);
    const uint32_t b_off = (uint32_t)(((l & 7) + ((l >> 4) & 1) * 8) * RSB + ((l >> 3) & 1) * 16);

    for (int i = 0; i < NCHUNK; i++) {
        const int slot = i % 3;
        if (i + 2 < NCHUNK && tid == 0) {
            const int s2 = (i + 2) % 3;
            MBAR_EXPECT(mbb + 8 * s2, 2 * STAGE);
            BULKCP(sb + s2 * STAGE, Asrc + (size_t)(i + 2) * STAGE, STAGE, mbb + 8 * s2);
            BULKCP(sb + (3 + s2) * STAGE, Bsrc + (size_t)(i + 2) * STAGE, STAGE, mbb + 8 * s2);
        }
        MBAR_WAIT(mbb + 8 * slot, (i / 3) & 1);

        const uint32_t abase = sb + slot * STAGE + (uint32_t)(wm * 64) * RSB + a_off;
        const uint32_t bbase = sb + (3 + slot) * STAGE + (uint32_t)(wn * 32) * RSB + b_off;
#pragma unroll
        for (int ks = 0; ks < 4; ks++) {
            uint32_t af[4][4], bf[2][4];
#pragma unroll
            for (int mt = 0; mt < 4; mt++)
                LDSM_X4(af[mt][0], af[mt][1], af[mt][2], af[mt][3],
                        abase + mt * (16 * RSB) + ks * 32);
#pragma unroll
            for (int g = 0; g < 2; g++)
                LDSM_X4(bf[g][0], bf[g][1], bf[g][2], bf[g][3],
                        bbase + g * (16 * RSB) + ks * 32);
#pragma unroll
            for (int mt = 0; mt < 4; mt++)
#pragma unroll
                for (int nt = 0; nt < 4; nt++)
                    mma16816(acc[mt][nt], af[mt], bf[nt >> 1][(nt & 1) * 2],
                             bf[nt >> 1][(nt & 1) * 2 + 1]);
        }
        __syncthreads();
    }

    const int mode = QKV ? (n0 >> 10) : 3;   // 0=Q, 1=K, 2=V(transpose), 3=fp32 C
    if (mode == 2) {
        __half* sT = (__half*)dsm;
#pragma unroll
        for (int mt = 0; mt < 4; mt++) {
#pragma unroll
            for (int nt = 0; nt < 4; nt++) {
                const int cl = wn * 32 + nt * 8 + (l & 3) * 2;
                const int rl = wm * 64 + mt * 16 + (l >> 2);
#pragma unroll
                for (int rr = 0; rr < 2; rr++) {
                    sT[(size_t)cl * 136 + rl + rr * 8]       =
                        __float2half_rn(acc[mt][nt][rr * 2 + 0]);
                    sT[(size_t)(cl + 1) * 136 + rl + rr * 8] =
                        __float2half_rn(acc[mt][nt][rr * 2 + 1]);
                }
            }
        }
        __syncthreads();
        const int cl = tid & 127, half_ = tid >> 7;
        const int gcol = (n0 - 2048) + cl;
        const int hh = gcol >> 6, d = gcol & 63;
        const int token0 = m0 + half_ * 64;
        const int bb = token0 >> 11, t = token0 & 2047;
        const int kb = t >> 6;
        const size_t base = ((size_t)((bb * NH + hh) * NBLK + kb)) * VTILE_H + (size_t)d * 72;
        const __half* src = sT + (size_t)cl * 136 + half_ * 64;
#pragma unroll
        for (int j8 = 0; j8 < 8; j8++)
            *(uint4*)(Va + base + j8 * 8) = *(const uint4*)(src + j8 * 8);
        return;
    }

#pragma unroll
    for (int mt = 0; mt < 4; mt++) {
#pragma unroll
        for (int nt = 0; nt < 4; nt++) {
            const int mr = m0 + wm * 64 + mt * 16 + (l >> 2);
            const int nc = n0 + wn * 32 + nt * 8 + (l & 3) * 2;
            if (mode == 3) {
                *(float2*)(C + (size_t)mr * DIM + nc) =
                    make_float2(acc[mt][nt][0], acc[mt][nt][1]);
                *(float2*)(C + (size_t)(mr + 8) * DIM + nc) =
                    make_float2(acc[mt][nt][2], acc[mt][nt][3]);
            } else {
                const int cl = nc & 1023;
                const int hh = cl >> 6, d = cl & 63;
                __half* dst = (mode == 0) ? Qa : Ka;
#pragma unroll
                for (int rr = 0; rr < 2; rr++) {
                    const int row = mr + rr * 8;
                    const int bb = row >> 11, t = row & 2047;
                    const size_t base = ((size_t)((bb * NH + hh) * NBLK + (t >> 6))) * ATILE_H
                                      + (size_t)(t & 63) * 136;
                    __half hx, lx, hy, ly;
                    split2h(acc[mt][nt][rr * 2 + 0], hx, lx);
                    split2h(acc[mt][nt][rr * 2 + 1], hy, ly);
                    *(uint32_t*)(dst + base + d) = pack2h(hx, hy);
                    *(uint32_t*)(dst + base + 64 + d) =
                        (mode == 0) ? pack2h(lx, ly) : pack2h(hx, hy);
                }
            }
        }
    }
}

// ---------------- bulk-copy tensor-core block-sparse flash attention ----------------
// Q in registers (staged via K1).  QK: 2-term K=128.  PV: hi-only K=64.
__global__ void __launch_bounds__(128, 4)
attn_mma(const __half* __restrict__ Qa, const __half* __restrict__ Ka,
         const __half* __restrict__ Va, __half* __restrict__ Oc)
{
    extern __shared__ char sm[];
    const uint32_t sb = smem_u32(sm);
    const uint32_t oK = 0, oV = 2 * ATILE;

    const int tid = threadIdx.x, wid = tid >> 5, l = tid & 31;
    const int qb = blockIdx.x, h = blockIdx.y, b = blockIdx.z;
    const size_t bh = (size_t)(b * NH + h);

    const uint32_t mbQ = sb + 2 * ATILE + 2 * VTILE;  // +0 Q, +8 stage0, +16 stage1
    if (tid == 0) {
        MBAR_INIT(mbQ, 1); MBAR_INIT(mbQ + 8, 1); MBAR_INIT(mbQ + 16, 1);
    }
    __syncthreads();

    uint32_t am = 0;
#pragma unroll
    for (int kb = 0; kb < NBLK; kb++)
        am |= (g_bm[qb * NBLK + kb] ? 1u : 0u) << kb;

    int kb_cur = __ffs(am) - 1;              // >= 0 (col 0 is global)
    am &= am - 1;

    const char* Kbase = (const char*)Ka + bh * NBLK * (size_t)ATILE;
    const char* Vbase = (const char*)Va + bh * NBLK * (size_t)VTILE;

    if (tid == 0) {
        MBAR_EXPECT(mbQ, ATILE);
        BULKCP(sb + oK + ATILE, (const char*)Qa + (bh * NBLK + qb) * (size_t)ATILE, ATILE, mbQ); // Q -> K1
        MBAR_EXPECT(mbQ + 8, ATILE + VTILE);
        BULKCP(sb + oK, Kbase + (size_t)kb_cur * ATILE, ATILE, mbQ + 8);
        BULKCP(sb + oV, Vbase + (size_t)kb_cur * VTILE, VTILE, mbQ + 8);
    }

    const uint32_t a_off = (uint32_t)((l & 15) * ARS + (l >> 4) * 16);
    const uint32_t b_off = (uint32_t)(((l & 7) + ((l >> 4) & 1) * 8) * ARS + ((l >> 3) & 1) * 16);
    const uint32_t v_off = (uint32_t)(((l & 7) + ((l >> 4) & 1) * 8) * VRS + ((l >> 3) & 1) * 16);

    // Q fragments -> registers (staged in K1)
    MBAR_WAIT(mbQ, 0);
    uint32_t qf[8][4];
    {
        const uint32_t aQ = sb + oK + ATILE + (uint32_t)(wid * 16) * ARS + a_off;
#pragma unroll
        for (int ks = 0; ks < 8; ks++)
            LDSM_X4(qf[ks][0], qf[ks][1], qf[ks][2], qf[ks][3], aQ + ks * 32);
    }
    __syncthreads();                          // K1 free for prefetch

    float o[8][4];
#pragma unroll
    for (int nt = 0; nt < 8; nt++)
#pragma unroll
        for (int q = 0; q < 4; q++) o[nt][q] = 0.f;
    float m0 = -INFINITY, m1 = -INFINITY, l0 = 0.f, l1 = 0.f;
    const float scale = 0.125f;

    int sbuf = 0;
    int par0 = 0, par1 = 0;
    while (kb_cur >= 0) {
        const int kb_nxt = am ? (__ffs(am) - 1) : -1;
        am &= am - 1;

        if (kb_nxt >= 0 && tid == 0) {
            const int s2 = sbuf ^ 1;
            MBAR_EXPECT(mbQ + 8 + 8 * s2, ATILE + VTILE);
            BULKCP(sb + oK + s2 * ATILE, Kbase + (size_t)kb_nxt * ATILE, ATILE, mbQ + 8 + 8 * s2);
            BULKCP(sb + oV + s2 * VTILE, Vbase + (size_t)kb_nxt * VTILE, VTILE, mbQ + 8 + 8 * s2);
        }

        if (sbuf == 0) { MBAR_WAIT(mbQ + 8, par0); par0 ^= 1; }
        else           { MBAR_WAIT(mbQ + 16, par1); par1 ^= 1; }

        const uint32_t bK = sb + oK + sbuf * ATILE + b_off;
        const uint32_t bV = sb + oV + sbuf * VTILE + v_off;

        // ---- S = Q K^T, K=128 ----
        float s[8][4];
#pragma unroll
        for (int nt = 0; nt < 8; nt++)
#pragma unroll
            for (int q = 0; q < 4; q++) s[nt][q] = 0.f;
#pragma unroll
        for (int ks = 0; ks < 8; ks++) {
            uint32_t bf[4][4];
#pragma unroll
            for (int g = 0; g < 4; g++)
                LDSM_X4(bf[g][0], bf[g][1], bf[g][2], bf[g][3],
                        bK + g * (16 * ARS) + ks * 32);
#pragma unroll
            for (int nt = 0; nt < 8; nt++)
                mma16816(s[nt], qf[ks], bf[nt >> 1][(nt & 1) * 2], bf[nt >> 1][(nt & 1) * 2 + 1]);
        }

        // ---- online softmax; P_hi fragments in registers ----
        float vm0 = -INFINITY, vm1 = -INFINITY;
#pragma unroll
        for (int nt = 0; nt < 8; nt++) {
#pragma unroll
            for (int q = 0; q < 4; q++) s[nt][q] *= scale;
            vm0 = fmaxf(vm0, fmaxf(s[nt][0], s[nt][1]));
            vm1 = fmaxf(vm1, fmaxf(s[nt][2], s[nt][3]));
        }
        vm0 = fmaxf(vm0, __shfl_xor_sync(0xffffffff, vm0, 1));
        vm0 = fmaxf(vm0, __shfl_xor_sync(0xffffffff, vm0, 2));
        vm1 = fmaxf(vm1, __shfl_xor_sync(0xffffffff, vm1, 1));
        vm1 = fmaxf(vm1, __shfl_xor_sync(0xffffffff, vm1, 2));

        const float mn0 = fmaxf(m0, vm0), mn1 = fmaxf(m1, vm1);
        const float al0 = __expf(m0 - mn0), al1 = __expf(m1 - mn1);
        m0 = mn0; m1 = mn1;

        uint32_t phi0[8], phi1[8];
        float rs0 = 0.f, rs1 = 0.f;
#pragma unroll
        for (int nt = 0; nt < 8; nt++) {
            float p00 = __expf(s[nt][0] - mn0), p01 = __expf(s[nt][1] - mn0);
            float p10 = __expf(s[nt][2] - mn1), p11 = __expf(s[nt][3] - mn1);
            rs0 += p00 + p01; rs1 += p10 + p11;
            phi0[nt] = pack2h(__float2half_rn(p00), __float2half_rn(p01));
            phi1[nt] = pack2h(__float2half_rn(p10), __float2half_rn(p11));
            o[nt][0] *= al0; o[nt][1] *= al0;
            o[nt][2] *= al1; o[nt][3] *= al1;
        }
        rs0 += __shfl_xor_sync(0xffffffff, rs0, 1);
        rs0 += __shfl_xor_sync(0xffffffff, rs0, 2);
        rs1 += __shfl_xor_sync(0xffffffff, rs1, 1);
        rs1 += __shfl_xor_sync(0xffffffff, rs1, 2);
        l0 = l0 * al0 + rs0;
        l1 = l1 * al1 + rs1;

        // ---- O += P_hi Vt^T, K=64 ----
#pragma unroll
        for (int ks = 0; ks < 4; ks++) {
            uint32_t af[4], bf[4][4];
            af[0] = phi0[2 * ks];     af[1] = phi1[2 * ks];
            af[2] = phi0[2 * ks + 1]; af[3] = phi1[2 * ks + 1];
#pragma unroll
            for (int g = 0; g < 4; g++)
                LDSM_X4(bf[g][0], bf[g][1], bf[g][2], bf[g][3],
                        bV + g * (16 * VRS) + ks * 32);
#pragma unroll
            for (int nt = 0; nt < 8; nt++)
                mma16816(o[nt], af, bf[nt >> 1][(nt & 1) * 2], bf[nt >> 1][(nt & 1) * 2 + 1]);
        }

        __syncthreads();                      // buffer recycle guard
        kb_cur = kb_nxt;
        sbuf ^= 1;
    }

    // epilogue: write Oc in GEMM-tiled layout (hi only)
    const float inv0 = 1.f / l0, inv1 = 1.f / l1;
    const int r0 = qb * 64 + wid * 16 + (l >> 2);
    const int c0 = h * 64 + (l & 3) * 2;
#pragma unroll
    for (int nt = 0; nt < 8; nt++) {
        const int col = c0 + nt * 8;
#pragma unroll
        for (int rr = 0; rr < 2; rr++) {
            const float inv = rr ? inv1 : inv0;
            const int row = b * SEQ + r0 + rr * 8;
            const size_t idx = ((size_t)((row >> 7) * 16 + (col >> 6))) * STAGE_H
                             + (row & 127) * 72 + (col & 63);
            __half hx = __float2half_rn(o[nt][rr * 2 + 0] * inv);
            __half hy = __float2half_rn(o[nt][rr * 2 + 1] * inv);
            *(uint32_t*)(Oc + idx) = pack2h(hx, hy);
        }
    }
}

// ---------------- launcher ----------------
extern "C" void kernel_launch(void* const* d_in, const int* in_sizes, int n_in,
                              void* d_out, int out_size)
{
    const float* X  = (const float*)d_in[0];
    const float* Wq = (const float*)d_in[1];
    const float* Wk = (const float*)d_in[2];
    const float* Wv = (const float*)d_in[3];
    const float* Wo = (const float*)d_in[4];
    const unsigned char* mask = (const unsigned char*)d_in[5];
    float* out = (float*)d_out;

    __half *Xc, *Oc, *Wqkv, *Woc, *Qa, *Ka, *Va;
    cudaGetSymbolAddress((void**)&Xc, g_Xc);
    cudaGetSymbolAddress((void**)&Oc, g_Oc);
    cudaGetSymbolAddress((void**)&Wqkv, g_Wqkv);
    cudaGetSymbolAddress((void**)&Woc, g_Wo);
    cudaGetSymbolAddress((void**)&Qa, g_Qa);
    cudaGetSymbolAddress((void**)&Ka, g_Ka);
    cudaGetSymbolAddress((void**)&Va, g_Va);

    cudaFuncSetAttribute(gemm_mma<true>,  cudaFuncAttributeMaxDynamicSharedMemorySize, SM_TOTAL);
    cudaFuncSetAttribute(gemm_mma<false>, cudaFuncAttributeMaxDynamicSharedMemorySize, SM_TOTAL);
    cudaFuncSetAttribute(attn_mma, cudaFuncAttributeMaxDynamicSharedMemorySize, ASM_TOTAL);

    build_block_mask<<<1, 1024>>>(mask);                                          // 1
    conv_act<<<(MROWS * DIM + 255) / 256, 256>>>(X, Xc, MROWS);                   // 2
    conv_wgt_all<<<(4 * DIM * DIM + 255) / 256, 256>>>(Wq, Wk, Wv, Wo, Wqkv, Woc);// 3

    dim3 qkvgrid(3 * DIM / TN, MROWS / TM);   // (24, 32)
    gemm_mma<true><<<qkvgrid, 256, SM_TOTAL>>>(Xc, Wqkv, Qa, Ka, Va, nullptr);    // 4

    dim3 agrid(NBLK, NH, BATCH);
    attn_mma<<<agrid, 128, ASM_TOTAL>>>(Qa, Ka, Va, Oc);                          // 5

    dim3 ogrid(DIM / TN, MROWS / TM);         // (8, 32)
    gemm_mma<false><<<ogrid, 256, SM_TOTAL>>>(Oc, Woc, nullptr, nullptr, nullptr, out); // 6
}

// round 16
// speedup vs baseline: 1.0973x; 1.0973x over previous
#include <cuda_runtime.h>
#include <cuda_fp16.h>
#include <math.h>
#include <stdint.h>

#define BATCH 2
#define SEQ   2048
#define DIM   1024
#define NH    16
#define HD    64
#define NBLK  32
#define BS    64
#define MROWS (BATCH * SEQ)        // 4096
#define KTOT  1024
#define KCH   64
#define NCHUNK (KTOT / KCH)        // 16
#define TM    128
#define TN    128
#define RSB   144                  // GEMM tile row stride bytes
#define STAGE 18432                // 128 rows * 144B
#define STAGE_H 9216
#define SM_TOTAL (6 * STAGE + 32)

// attention tiles: ALL hi-only, 64 rows x (128B data + 16B pad)
#define TRS   144
#define TILE  9216
#define TILE_H 4608
// smem: K0 @0, K1 @TILE, V0 @2T, V1 @3T, mbars @4T
#define ASM_TOTAL (4 * TILE + 32)  // 36896

// ---------------- device scratch (tiled, pre-padded layouts) ----------------
__device__ __half g_Xc[(size_t)32 * 16 * STAGE_H];
__device__ __half g_Oc[(size_t)32 * 16 * STAGE_H];
__device__ __half g_Wqkv[(size_t)24 * 16 * STAGE_H];
__device__ __half g_Wo[(size_t)8 * 16 * STAGE_H];
__device__ __half g_Qa[(size_t)32 * NBLK * TILE_H];       // [bh][qb] 64x72h, hi
__device__ __half g_Ka[(size_t)32 * NBLK * TILE_H];       // [bh][kb] hi
__device__ __half g_Va[(size_t)32 * NBLK * TILE_H];       // [bh][kb] Vt[d][j] hi
__device__ unsigned char g_bm[NBLK * NBLK];

// ---------------- helpers ----------------
__device__ __forceinline__ uint32_t smem_u32(const void* p) {
    uint32_t a;
    asm("{ .reg .u64 t; cvta.to.shared.u64 t, %1; cvt.u32.u64 %0, t; }" : "=r"(a) : "l"(p));
    return a;
}
#define LDSM_X4(r0, r1, r2, r3, addr) \
    asm volatile("ldmatrix.sync.aligned.m8n8.x4.shared.b16 {%0,%1,%2,%3}, [%4];" \
        : "=r"(r0), "=r"(r1), "=r"(r2), "=r"(r3) : "r"(addr))

#define MBAR_INIT(a, c) \
    asm volatile("mbarrier.init.shared.b64 [%0], %1;" :: "r"(a), "r"(c) : "memory")
#define MBAR_EXPECT(a, n) \
    asm volatile("mbarrier.arrive.expect_tx.shared.b64 _, [%0], %1;" :: "r"(a), "r"(n) : "memory")
#define BULKCP(dst, src, n, mb) \
    asm volatile("cp.async.bulk.shared::cluster.global.mbarrier::complete_tx::bytes [%0], [%1], %2, [%3];" \
        :: "r"(dst), "l"(src), "r"(n), "r"(mb) : "memory")
#define MBAR_WAIT(addr, par) do { \
    uint32_t _m = (addr), _p = (par), _d; \
    asm volatile("{ .reg .pred p; mbarrier.try_wait.parity.acquire.cta.shared::cta.b64 p, [%1], %2; selp.b32 %0,1,0,p; }" \
        : "=r"(_d) : "r"(_m), "r"(_p) : "memory"); \
    if (!_d) { \
        asm volatile("{ .reg .pred P; L1_%=: mbarrier.try_wait.parity.acquire.cta.shared::cta.b64 P, [%0], %1, 0x989680; @P bra.uni L2_%=; bra.uni L1_%=; L2_%=: }" \
            :: "r"(_m), "r"(_p) : "memory"); \
    } } while (0)

__device__ __forceinline__ void mma16816(float* c, const uint32_t* a, uint32_t b0, uint32_t b1) {
    asm volatile("mma.sync.aligned.m16n8k16.row.col.f32.f16.f16.f32 "
        "{%0,%1,%2,%3}, {%4,%5,%6,%7}, {%8,%9}, {%0,%1,%2,%3};"
        : "+f"(c[0]), "+f"(c[1]), "+f"(c[2]), "+f"(c[3])
        : "r"(a[0]), "r"(a[1]), "r"(a[2]), "r"(a[3]), "r"(b0), "r"(b1));
}
__device__ __forceinline__ uint32_t pack2h(__half a, __half b) {
    return (uint32_t)__half_as_ushort(a) | ((uint32_t)__half_as_ushort(b) << 16);
}

// ---------------- mask build (dtype-agnostic) ----------------
__global__ void build_block_mask(const unsigned char* __restrict__ m)
{
    const unsigned char b1 = m[1];
    int esz = (b1 == 0) ? 4 : (b1 == 1 ? 1 : 2);
    int idx = blockIdx.x * blockDim.x + threadIdx.x;
    if (idx >= NBLK * NBLK) return;
    int qb = idx / NBLK, kb = idx % NBLK;
    size_t elem = (size_t)(qb * BS) * SEQ + (size_t)kb * BS;
    bool allowed;
    if (esz == 1)      allowed = m[elem] != 0;
    else if (esz == 2) allowed = ((const unsigned short*)m)[elem] != 0;
    else               allowed = ((const unsigned int*)m)[elem] != 0;
    g_bm[idx] = allowed ? 1 : 0;
}

// ---------------- fp32 -> fp16 conversions into tiled layouts ----------------
__global__ void conv_act(const float* __restrict__ X, __half* __restrict__ out, int rows)
{
    int i = blockIdx.x * blockDim.x + threadIdx.x;
    if (i >= rows * DIM) return;
    int row = i >> 10, col = i & 1023;
    size_t idx = ((size_t)((row >> 7) * 16 + (col >> 6))) * STAGE_H
               + (row & 127) * 72 + (col & 63);
    out[idx] = __float2half_rn(X[i]);
}
__global__ void conv_wgt_all(const float* __restrict__ Wq, const float* __restrict__ Wk,
                             const float* __restrict__ Wv, const float* __restrict__ Wo,
                             __half* __restrict__ Wqkv, __half* __restrict__ Woc)
{
    int i = blockIdx.x * blockDim.x + threadIdx.x;
    if (i >= 4 * DIM * DIM) return;
    int w = i >> 20;
    int j = i & (DIM * DIM - 1);
    const float* W = (w == 0) ? Wq : (w == 1) ? Wk : (w == 2) ? Wv : Wo;
    int r = j >> 10, c = j & 1023;
    __half h = __float2half_rn(W[j]);
    if (w < 3) {
        int grow = w * 1024 + r;
        size_t idx = ((size_t)((grow >> 7) * 16 + (c >> 6))) * STAGE_H
                   + (grow & 127) * 72 + (c & 63);
        Wqkv[idx] = h;
    } else {
        size_t idx = ((size_t)((r >> 7) * 16 + (c >> 6))) * STAGE_H
                   + (r & 127) * 72 + (c & 63);
        Woc[idx] = h;
    }
}

// ---------------- bulk-copy pipelined mma.sync GEMM (8 warps, 64x32) ----------------
// QKV=true: B is Wqkv [3072,1024] tiled; epilogue by column segment (all hi-only):
//   n<1024 -> Qa;  n<2048 -> Ka;  else -> Va (transposed).
template<bool QKV>
__global__ void __launch_bounds__(256, 2)
gemm_mma(const __half* __restrict__ A, const __half* __restrict__ Bw,
         __half* __restrict__ Qa, __half* __restrict__ Ka,
         __half* __restrict__ Va, float* __restrict__ C)
{
    extern __shared__ char dsm[];
    const uint32_t sb = smem_u32(dsm);
    const int tid = threadIdx.x;
    const int wid = tid >> 5, l = tid & 31;
    const int wm = wid >> 2, wn = wid & 3;
    const int m0 = blockIdx.y * TM, n0 = blockIdx.x * TN;

    const uint32_t mbb = sb + 6 * STAGE;
    if (tid == 0) {
        MBAR_INIT(mbb, 1); MBAR_INIT(mbb + 8, 1); MBAR_INIT(mbb + 16, 1);
    }
    __syncthreads();

    const char* Asrc = (const char*)A + (size_t)blockIdx.y * 16 * STAGE;
    const char* Bsrc = (const char*)Bw + (size_t)blockIdx.x * 16 * STAGE;

    if (tid == 0) {
#pragma unroll
        for (int s = 0; s < 2; s++) {
            MBAR_EXPECT(mbb + 8 * s, 2 * STAGE);
            BULKCP(sb + s * STAGE, Asrc + (size_t)s * STAGE, STAGE, mbb + 8 * s);
            BULKCP(sb + (3 + s) * STAGE, Bsrc + (size_t)s * STAGE, STAGE, mbb + 8 * s);
        }
    }

    float acc[4][4][4];
#pragma unroll
    for (int i = 0; i < 4; i++)
#pragma unroll
        for (int j = 0; j < 4; j++)
#pragma unroll
            for (int q = 0; q < 4; q++) acc[i][j][q] = 0.f;

    const uint32_t a_off = (uint32_t)((l & 15) * RSB + (l >> 4) * 16);
    const uint32_t b_off = (uint32_t)(((l & 7) + ((l >> 4) & 1) * 8) * RSB + ((l >> 3) & 1) * 16);

    for (int i = 0; i < NCHUNK; i++) {
        const int slot = i % 3;
        if (i + 2 < NCHUNK && tid == 0) {
            const int s2 = (i + 2) % 3;
            MBAR_EXPECT(mbb + 8 * s2, 2 * STAGE);
            BULKCP(sb + s2 * STAGE, Asrc + (size_t)(i + 2) * STAGE, STAGE, mbb + 8 * s2);
            BULKCP(sb + (3 + s2) * STAGE, Bsrc + (size_t)(i + 2) * STAGE, STAGE, mbb + 8 * s2);
        }
        MBAR_WAIT(mbb + 8 * slot, (i / 3) & 1);

        const uint32_t abase = sb + slot * STAGE + (uint32_t)(wm * 64) * RSB + a_off;
        const uint32_t bbase = sb + (3 + slot) * STAGE + (uint32_t)(wn * 32) * RSB + b_off;
#pragma unroll
        for (int ks = 0; ks < 4; ks++) {
            uint32_t af[4][4], bf[2][4];
#pragma unroll
            for (int mt = 0; mt < 4; mt++)
                LDSM_X4(af[mt][0], af[mt][1], af[mt][2], af[mt][3],
                        abase + mt * (16 * RSB) + ks * 32);
#pragma unroll
            for (int g = 0; g < 2; g++)
                LDSM_X4(bf[g][0], bf[g][1], bf[g][2], bf[g][3],
                        bbase + g * (16 * RSB) + ks * 32);
#pragma unroll
            for (int mt = 0; mt < 4; mt++)
#pragma unroll
                for (int nt = 0; nt < 4; nt++)
                    mma16816(acc[mt][nt], af[mt], bf[nt >> 1][(nt & 1) * 2],
                             bf[nt >> 1][(nt & 1) * 2 + 1]);
        }
        __syncthreads();
    }

    const int mode = QKV ? (n0 >> 10) : 3;   // 0=Q, 1=K, 2=V(transpose), 3=fp32 C
    if (mode == 2) {
        __half* sT = (__half*)dsm;
#pragma unroll
        for (int mt = 0; mt < 4; mt++) {
#pragma unroll
            for (int nt = 0; nt < 4; nt++) {
                const int cl = wn * 32 + nt * 8 + (l & 3) * 2;
                const int rl = wm * 64 + mt * 16 + (l >> 2);
#pragma unroll
                for (int rr = 0; rr < 2; rr++) {
                    sT[(size_t)cl * 136 + rl + rr * 8]       =
                        __float2half_rn(acc[mt][nt][rr * 2 + 0]);
                    sT[(size_t)(cl + 1) * 136 + rl + rr * 8] =
                        __float2half_rn(acc[mt][nt][rr * 2 + 1]);
                }
            }
        }
        __syncthreads();
        const int cl = tid & 127, half_ = tid >> 7;
        const int gcol = (n0 - 2048) + cl;
        const int hh = gcol >> 6, d = gcol & 63;
        const int token0 = m0 + half_ * 64;
        const int bb = token0 >> 11, t = token0 & 2047;
        const int kb = t >> 6;
        const size_t base = ((size_t)((bb * NH + hh) * NBLK + kb)) * TILE_H + (size_t)d * 72;
        const __half* src = sT + (size_t)cl * 136 + half_ * 64;
#pragma unroll
        for (int j8 = 0; j8 < 8; j8++)
            *(uint4*)(Va + base + j8 * 8) = *(const uint4*)(src + j8 * 8);
        return;
    }

#pragma unroll
    for (int mt = 0; mt < 4; mt++) {
#pragma unroll
        for (int nt = 0; nt < 4; nt++) {
            const int mr = m0 + wm * 64 + mt * 16 + (l >> 2);
            const int nc = n0 + wn * 32 + nt * 8 + (l & 3) * 2;
            if (mode == 3) {
                *(float2*)(C + (size_t)mr * DIM + nc) =
                    make_float2(acc[mt][nt][0], acc[mt][nt][1]);
                *(float2*)(C + (size_t)(mr + 8) * DIM + nc) =
                    make_float2(acc[mt][nt][2], acc[mt][nt][3]);
            } else {
                const int cl = nc & 1023;
                const int hh = cl >> 6, d = cl & 63;
                __half* dst = (mode == 0) ? Qa : Ka;
#pragma unroll
                for (int rr = 0; rr < 2; rr++) {
                    const int row = mr + rr * 8;
                    const int bb = row >> 11, t = row & 2047;
                    const size_t base = ((size_t)((bb * NH + hh) * NBLK + (t >> 6))) * TILE_H
                                      + (size_t)(t & 63) * 72;
                    *(uint32_t*)(dst + base + d) =
                        pack2h(__float2half_rn(acc[mt][nt][rr * 2 + 0]),
                               __float2half_rn(acc[mt][nt][rr * 2 + 1]));
                }
            }
        }
    }
}

// ---------------- bulk-copy tensor-core block-sparse flash attention ----------------
// All-hi fp16: QK K=64, PV K=64. Q in registers (staged via K1 buffer).
__global__ void __launch_bounds__(128, 4)
attn_mma(const __half* __restrict__ Qa, const __half* __restrict__ Ka,
         const __half* __restrict__ Va, __half* __restrict__ Oc)
{
    extern __shared__ char sm[];
    const uint32_t sb = smem_u32(sm);
    const uint32_t oK = 0, oV = 2 * TILE;

    const int tid = threadIdx.x, wid = tid >> 5, l = tid & 31;
    const int qb = blockIdx.x, h = blockIdx.y, b = blockIdx.z;
    const size_t bh = (size_t)(b * NH + h);

    const uint32_t mbQ = sb + 4 * TILE;      // +0 Q, +8 stage0, +16 stage1
    if (tid == 0) {
        MBAR_INIT(mbQ, 1); MBAR_INIT(mbQ + 8, 1); MBAR_INIT(mbQ + 16, 1);
    }
    __syncthreads();

    uint32_t am = 0;
#pragma unroll
    for (int kb = 0; kb < NBLK; kb++)
        am |= (g_bm[qb * NBLK + kb] ? 1u : 0u) << kb;

    int kb_cur = __ffs(am) - 1;              // >= 0 (col 0 is global)
    am &= am - 1;

    const char* Kbase = (const char*)Ka + bh * NBLK * (size_t)TILE;
    const char* Vbase = (const char*)Va + bh * NBLK * (size_t)TILE;

    if (tid == 0) {
        MBAR_EXPECT(mbQ, TILE);
        BULKCP(sb + oK + TILE, (const char*)Qa + (bh * NBLK + qb) * (size_t)TILE, TILE, mbQ); // Q -> K1
        MBAR_EXPECT(mbQ + 8, 2 * TILE);
        BULKCP(sb + oK, Kbase + (size_t)kb_cur * TILE, TILE, mbQ + 8);
        BULKCP(sb + oV, Vbase + (size_t)kb_cur * TILE, TILE, mbQ + 8);
    }

    const uint32_t a_off = (uint32_t)((l & 15) * TRS + (l >> 4) * 16);
    const uint32_t b_off = (uint32_t)(((l & 7) + ((l >> 4) & 1) * 8) * TRS + ((l >> 3) & 1) * 16);

    // Q fragments -> registers (staged in K1)
    MBAR_WAIT(mbQ, 0);
    uint32_t qf[4][4];
    {
        const uint32_t aQ = sb + oK + TILE + (uint32_t)(wid * 16) * TRS + a_off;
#pragma unroll
        for (int ks = 0; ks < 4; ks++)
            LDSM_X4(qf[ks][0], qf[ks][1], qf[ks][2], qf[ks][3], aQ + ks * 32);
    }
    __syncthreads();                          // K1 free for prefetch

    float o[8][4];
#pragma unroll
    for (int nt = 0; nt < 8; nt++)
#pragma unroll
        for (int q = 0; q < 4; q++) o[nt][q] = 0.f;
    float m0 = -INFINITY, m1 = -INFINITY, l0 = 0.f, l1 = 0.f;
    const float scale = 0.125f;

    int sbuf = 0;
    int par0 = 0, par1 = 0;
    while (kb_cur >= 0) {
        const int kb_nxt = am ? (__ffs(am) - 1) : -1;
        am &= am - 1;

        if (kb_nxt >= 0 && tid == 0) {
            const int s2 = sbuf ^ 1;
            MBAR_EXPECT(mbQ + 8 + 8 * s2, 2 * TILE);
            BULKCP(sb + oK + s2 * TILE, Kbase + (size_t)kb_nxt * TILE, TILE, mbQ + 8 + 8 * s2);
            BULKCP(sb + oV + s2 * TILE, Vbase + (size_t)kb_nxt * TILE, TILE, mbQ + 8 + 8 * s2);
        }

        if (sbuf == 0) { MBAR_WAIT(mbQ + 8, par0); par0 ^= 1; }
        else           { MBAR_WAIT(mbQ + 16, par1); par1 ^= 1; }

        const uint32_t bK = sb + oK + sbuf * TILE + b_off;
        const uint32_t bV = sb + oV + sbuf * TILE + b_off;

        // ---- S = Q K^T, K=64 (hi only) ----
        float s[8][4];
#pragma unroll
        for (int nt = 0; nt < 8; nt++)
#pragma unroll
            for (int q = 0; q < 4; q++) s[nt][q] = 0.f;
#pragma unroll
        for (int ks = 0; ks < 4; ks++) {
            uint32_t bf[4][4];
#pragma unroll
            for (int g = 0; g < 4; g++)
                LDSM_X4(bf[g][0], bf[g][1], bf[g][2], bf[g][3],
                        bK + g * (16 * TRS) + ks * 32);
#pragma unroll
            for (int nt = 0; nt < 8; nt++)
                mma16816(s[nt], qf[ks], bf[nt >> 1][(nt & 1) * 2], bf[nt >> 1][(nt & 1) * 2 + 1]);
        }

        // ---- online softmax; P_hi fragments in registers ----
        float vm0 = -INFINITY, vm1 = -INFINITY;
#pragma unroll
        for (int nt = 0; nt < 8; nt++) {
#pragma unroll
            for (int q = 0; q < 4; q++) s[nt][q] *= scale;
            vm0 = fmaxf(vm0, fmaxf(s[nt][0], s[nt][1]));
            vm1 = fmaxf(vm1, fmaxf(s[nt][2], s[nt][3]));
        }
        vm0 = fmaxf(vm0, __shfl_xor_sync(0xffffffff, vm0, 1));
        vm0 = fmaxf(vm0, __shfl_xor_sync(0xffffffff, vm0, 2));
        vm1 = fmaxf(vm1, __shfl_xor_sync(0xffffffff, vm1, 1));
        vm1 = fmaxf(vm1, __shfl_xor_sync(0xffffffff, vm1, 2));

        const float mn0 = fmaxf(m0, vm0), mn1 = fmaxf(m1, vm1);
        const float al0 = __expf(m0 - mn0), al1 = __expf(m1 - mn1);
        m0 = mn0; m1 = mn1;

        uint32_t phi0[8], phi1[8];
        float rs0 = 0.f, rs1 = 0.f;
#pragma unroll
        for (int nt = 0; nt < 8; nt++) {
            float p00 = __expf(s[nt][0] - mn0), p01 = __expf(s[nt][1] - mn0);
            float p10 = __expf(s[nt][2] - mn1), p11 = __expf(s[nt][3] - mn1);
            rs0 += p00 + p01; rs1 += p10 + p11;
            phi0[nt] = pack2h(__float2half_rn(p00), __float2half_rn(p01));
            phi1[nt] = pack2h(__float2half_rn(p10), __float2half_rn(p11));
            o[nt][0] *= al0; o[nt][1] *= al0;
            o[nt][2] *= al1; o[nt][3] *= al1;
        }
        rs0 += __shfl_xor_sync(0xffffffff, rs0, 1);
        rs0 += __shfl_xor_sync(0xffffffff, rs0, 2);
        rs1 += __shfl_xor_sync(0xffffffff, rs1, 1);
        rs1 += __shfl_xor_sync(0xffffffff, rs1, 2);
        l0 = l0 * al0 + rs0;
        l1 = l1 * al1 + rs1;

        // ---- O += P_hi Vt^T, K=64 ----
#pragma unroll
        for (int ks = 0; ks < 4; ks++) {
            uint32_t af[4], bf[4][4];
            af[0] = phi0[2 * ks];     af[1] = phi1[2 * ks];
            af[2] = phi0[2 * ks + 1]; af[3] = phi1[2 * ks + 1];
#pragma unroll
            for (int g = 0; g < 4; g++)
                LDSM_X4(bf[g][0], bf[g][1], bf[g][2], bf[g][3],
                        bV + g * (16 * TRS) + ks * 32);
#pragma unroll
            for (int nt = 0; nt < 8; nt++)
                mma16816(o[nt], af, bf[nt >> 1][(nt & 1) * 2], bf[nt >> 1][(nt & 1) * 2 + 1]);
        }

        __syncthreads();                      // buffer recycle guard
        kb_cur = kb_nxt;
        sbuf ^= 1;
    }

    // epilogue: write Oc in GEMM-tiled layout (hi only)
    const float inv0 = 1.f / l0, inv1 = 1.f / l1;
    const int r0 = qb * 64 + wid * 16 + (l >> 2);
    const int c0 = h * 64 + (l & 3) * 2;
#pragma unroll
    for (int nt = 0; nt < 8; nt++) {
        const int col = c0 + nt * 8;
#pragma unroll
        for (int rr = 0; rr < 2; rr++) {
            const float inv = rr ? inv1 : inv0;
            const int row = b * SEQ + r0 + rr * 8;
            const size_t idx = ((size_t)((row >> 7) * 16 + (col >> 6))) * STAGE_H
                             + (row & 127) * 72 + (col & 63);
            __half hx = __float2half_rn(o[nt][rr * 2 + 0] * inv);
            __half hy = __float2half_rn(o[nt][rr * 2 + 1] * inv);
            *(uint32_t*)(Oc + idx) = pack2h(hx, hy);
        }
    }
}

// ---------------- launcher ----------------
extern "C" void kernel_launch(void* const* d_in, const int* in_sizes, int n_in,
                              void* d_out, int out_size)
{
    const float* X  = (const float*)d_in[0];
    const float* Wq = (const float*)d_in[1];
    const float* Wk = (const float*)d_in[2];
    const float* Wv = (const float*)d_in[3];
    const float* Wo = (const float*)d_in[4];
    const unsigned char* mask = (const unsigned char*)d_in[5];
    float* out = (float*)d_out;

    __half *Xc, *Oc, *Wqkv, *Woc, *Qa, *Ka, *Va;
    cudaGetSymbolAddress((void**)&Xc, g_Xc);
    cudaGetSymbolAddress((void**)&Oc, g_Oc);
    cudaGetSymbolAddress((void**)&Wqkv, g_Wqkv);
    cudaGetSymbolAddress((void**)&Woc, g_Wo);
    cudaGetSymbolAddress((void**)&Qa, g_Qa);
    cudaGetSymbolAddress((void**)&Ka, g_Ka);
    cudaGetSymbolAddress((void**)&Va, g_Va);

    cudaFuncSetAttribute(gemm_mma<true>,  cudaFuncAttributeMaxDynamicSharedMemorySize, SM_TOTAL);
    cudaFuncSetAttribute(gemm_mma<false>, cudaFuncAttributeMaxDynamicSharedMemorySize, SM_TOTAL);
    cudaFuncSetAttribute(attn_mma, cudaFuncAttributeMaxDynamicSharedMemorySize, ASM_TOTAL);

    build_block_mask<<<1, 1024>>>(mask);                                          // 1
    conv_act<<<(MROWS * DIM + 255) / 256, 256>>>(X, Xc, MROWS);                   // 2
    conv_wgt_all<<<(4 * DIM * DIM + 255) / 256, 256>>>(Wq, Wk, Wv, Wo, Wqkv, Woc);// 3

    dim3 qkvgrid(3 * DIM / TN, MROWS / TM);   // (24, 32)
    gemm_mma<true><<<qkvgrid, 256, SM_TOTAL>>>(Xc, Wqkv, Qa, Ka, Va, nullptr);    // 4

    dim3 agrid(NBLK, NH, BATCH);
    attn_mma<<<agrid, 128, ASM_TOTAL>>>(Qa, Ka, Va, Oc);                          // 5

    dim3 ogrid(DIM / TN, MROWS / TM);         // (8, 32)
    gemm_mma<false><<<ogrid, 256, SM_TOTAL>>>(Oc, Woc, nullptr, nullptr, nullptr, out); // 6
}

// round 17
// speedup vs baseline: 1.1116x; 1.0130x over previous
#include <cuda_runtime.h>
#include <cuda_fp16.h>
#include <math.h>
#include <stdint.h>

#define BATCH 2
#define SEQ   2048
#define DIM   1024
#define NH    16
#define HD    64
#define NBLK  32
#define BS    64
#define MROWS (BATCH * SEQ)        // 4096
#define KTOT  1024
#define KCH   64
#define NCHUNK (KTOT / KCH)        // 16
#define TM    128
#define TN    128
#define RSB   144                  // GEMM tile row stride bytes
#define STAGE 18432                // 128 rows * 144B
#define STAGE_H 9216
#define SM_TOTAL (6 * STAGE + 32)

// attention tiles: hi-only, 64 rows x (128B data + 16B pad)
#define TRS   144
#define TILE  9216
#define TILE_H 4608
// smem: K0..K2 @0, V0..V2 @3*TILE, mbars @6*TILE
#define ASM_TOTAL (6 * TILE + 40)  // 55336

// ---------------- device scratch (tiled, pre-padded layouts) ----------------
__device__ __half g_Xc[(size_t)32 * 16 * STAGE_H];
__device__ __half g_Oc[(size_t)32 * 16 * STAGE_H];
__device__ __half g_Wqkv[(size_t)24 * 16 * STAGE_H];
__device__ __half g_Wo[(size_t)8 * 16 * STAGE_H];
__device__ __half g_Qa[(size_t)32 * NBLK * TILE_H];       // [bh][qb] 64x72h, hi
__device__ __half g_Ka[(size_t)32 * NBLK * TILE_H];       // [bh][kb] hi
__device__ __half g_Va[(size_t)32 * NBLK * TILE_H];       // [bh][kb] Vt[d][j] hi
__device__ unsigned char g_bm[NBLK * NBLK];

// ---------------- helpers ----------------
__device__ __forceinline__ uint32_t smem_u32(const void* p) {
    uint32_t a;
    asm("{ .reg .u64 t; cvta.to.shared.u64 t, %1; cvt.u32.u64 %0, t; }" : "=r"(a) : "l"(p));
    return a;
}
#define LDSM_X4(r0, r1, r2, r3, addr) \
    asm volatile("ldmatrix.sync.aligned.m8n8.x4.shared.b16 {%0,%1,%2,%3}, [%4];" \
        : "=r"(r0), "=r"(r1), "=r"(r2), "=r"(r3) : "r"(addr))

#define MBAR_INIT(a, c) \
    asm volatile("mbarrier.init.shared.b64 [%0], %1;" :: "r"(a), "r"(c) : "memory")
#define MBAR_EXPECT(a, n) \
    asm volatile("mbarrier.arrive.expect_tx.shared.b64 _, [%0], %1;" :: "r"(a), "r"(n) : "memory")
#define BULKCP(dst, src, n, mb) \
    asm volatile("cp.async.bulk.shared::cluster.global.mbarrier::complete_tx::bytes [%0], [%1], %2, [%3];" \
        :: "r"(dst), "l"(src), "r"(n), "r"(mb) : "memory")
#define MBAR_WAIT(addr, par) do { \
    uint32_t _m = (addr), _p = (par), _d; \
    asm volatile("{ .reg .pred p; mbarrier.try_wait.parity.acquire.cta.shared::cta.b64 p, [%1], %2; selp.b32 %0,1,0,p; }" \
        : "=r"(_d) : "r"(_m), "r"(_p) : "memory"); \
    if (!_d) { \
        asm volatile("{ .reg .pred P; L1_%=: mbarrier.try_wait.parity.acquire.cta.shared::cta.b64 P, [%0], %1, 0x989680; @P bra.uni L2_%=; bra.uni L1_%=; L2_%=: }" \
            :: "r"(_m), "r"(_p) : "memory"); \
    } } while (0)

__device__ __forceinline__ void mma16816(float* c, const uint32_t* a, uint32_t b0, uint32_t b1) {
    asm volatile("mma.sync.aligned.m16n8k16.row.col.f32.f16.f16.f32 "
        "{%0,%1,%2,%3}, {%4,%5,%6,%7}, {%8,%9}, {%0,%1,%2,%3};"
        : "+f"(c[0]), "+f"(c[1]), "+f"(c[2]), "+f"(c[3])
        : "r"(a[0]), "r"(a[1]), "r"(a[2]), "r"(a[3]), "r"(b0), "r"(b1));
}
__device__ __forceinline__ uint32_t pack2h(__half a, __half b) {
    return (uint32_t)__half_as_ushort(a) | ((uint32_t)__half_as_ushort(b) << 16);
}

// ---------------- mask build (dtype-agnostic) ----------------
__global__ void build_block_mask(const unsigned char* __restrict__ m)
{
    const unsigned char b1 = m[1];
    int esz = (b1 == 0) ? 4 : (b1 == 1 ? 1 : 2);
    int idx = blockIdx.x * blockDim.x + threadIdx.x;
    if (idx >= NBLK * NBLK) return;
    int qb = idx / NBLK, kb = idx % NBLK;
    size_t elem = (size_t)(qb * BS) * SEQ + (size_t)kb * BS;
    bool allowed;
    if (esz == 1)      allowed = m[elem] != 0;
    else if (esz == 2) allowed = ((const unsigned short*)m)[elem] != 0;
    else               allowed = ((const unsigned int*)m)[elem] != 0;
    g_bm[idx] = allowed ? 1 : 0;
}

// ---------------- fp32 -> fp16 conversions into tiled layouts ----------------
__global__ void conv_act(const float* __restrict__ X, __half* __restrict__ out, int rows)
{
    int i = blockIdx.x * blockDim.x + threadIdx.x;
    if (i >= rows * DIM) return;
    int row = i >> 10, col = i & 1023;
    size_t idx = ((size_t)((row >> 7) * 16 + (col >> 6))) * STAGE_H
               + (row & 127) * 72 + (col & 63);
    out[idx] = __float2half_rn(X[i]);
}
__global__ void conv_wgt_all(const float* __restrict__ Wq, const float* __restrict__ Wk,
                             const float* __restrict__ Wv, const float* __restrict__ Wo,
                             __half* __restrict__ Wqkv, __half* __restrict__ Woc)
{
    int i = blockIdx.x * blockDim.x + threadIdx.x;
    if (i >= 4 * DIM * DIM) return;
    int w = i >> 20;
    int j = i & (DIM * DIM - 1);
    const float* W = (w == 0) ? Wq : (w == 1) ? Wk : (w == 2) ? Wv : Wo;
    int r = j >> 10, c = j & 1023;
    __half h = __float2half_rn(W[j]);
    if (w < 3) {
        int grow = w * 1024 + r;
        size_t idx = ((size_t)((grow >> 7) * 16 + (c >> 6))) * STAGE_H
                   + (grow & 127) * 72 + (c & 63);
        Wqkv[idx] = h;
    } else {
        size_t idx = ((size_t)((r >> 7) * 16 + (c >> 6))) * STAGE_H
                   + (r & 127) * 72 + (c & 63);
        Woc[idx] = h;
    }
}

// ---------------- bulk-copy pipelined mma.sync GEMM (8 warps, 64x32) ----------------
template<bool QKV>
__global__ void __launch_bounds__(256, 2)
gemm_mma(const __half* __restrict__ A, const __half* __restrict__ Bw,
         __half* __restrict__ Qa, __half* __restrict__ Ka,
         __half* __restrict__ Va, float* __restrict__ C)
{
    extern __shared__ char dsm[];
    const uint32_t sb = smem_u32(dsm);
    const int tid = threadIdx.x;
    const int wid = tid >> 5, l = tid & 31;
    const int wm = wid >> 2, wn = wid & 3;
    const int m0 = blockIdx.y * TM, n0 = blockIdx.x * TN;

    const uint32_t mbb = sb + 6 * STAGE;
    if (tid == 0) {
        MBAR_INIT(mbb, 1); MBAR_INIT(mbb + 8, 1); MBAR_INIT(mbb + 16, 1);
    }
    __syncthreads();

    const char* Asrc = (const char*)A + (size_t)blockIdx.y * 16 * STAGE;
    const char* Bsrc = (const char*)Bw + (size_t)blockIdx.x * 16 * STAGE;

    if (tid == 0) {
#pragma unroll
        for (int s = 0; s < 2; s++) {
            MBAR_EXPECT(mbb + 8 * s, 2 * STAGE);
            BULKCP(sb + s * STAGE, Asrc + (size_t)s * STAGE, STAGE, mbb + 8 * s);
            BULKCP(sb + (3 + s) * STAGE, Bsrc + (size_t)s * STAGE, STAGE, mbb + 8 * s);
        }
    }

    float acc[4][4][4];
#pragma unroll
    for (int i = 0; i < 4; i++)
#pragma unroll
        for (int j = 0; j < 4; j++)
#pragma unroll
            for (int q = 0; q < 4; q++) acc[i][j][q] = 0.f;

    const uint32_t a_off = (uint32_t)((l & 15) * RSB + (l >> 4) * 16);
    const uint32_t b_off = (uint32_t)(((l & 7) + ((l >> 4) & 1) * 8) * RSB + ((l >> 3) & 1) * 16);

    for (int i = 0; i < NCHUNK; i++) {
        const int slot = i % 3;
        if (i + 2 < NCHUNK && tid == 0) {
            const int s2 = (i + 2) % 3;
            MBAR_EXPECT(mbb + 8 * s2, 2 * STAGE);
            BULKCP(sb + s2 * STAGE, Asrc + (size_t)(i + 2) * STAGE, STAGE, mbb + 8 * s2);
            BULKCP(sb + (3 + s2) * STAGE, Bsrc + (size_t)(i + 2) * STAGE, STAGE, mbb + 8 * s2);
        }
        MBAR_WAIT(mbb + 8 * slot, (i / 3) & 1);

        const uint32_t abase = sb + slot * STAGE + (uint32_t)(wm * 64) * RSB + a_off;
        const uint32_t bbase = sb + (3 + slot) * STAGE + (uint32_t)(wn * 32) * RSB + b_off;
#pragma unroll
        for (int ks = 0; ks < 4; ks++) {
            uint32_t af[4][4], bf[2][4];
#pragma unroll
            for (int mt = 0; mt < 4; mt++)
                LDSM_X4(af[mt][0], af[mt][1], af[mt][2], af[mt][3],
                        abase + mt * (16 * RSB) + ks * 32);
#pragma unroll
            for (int g = 0; g < 2; g++)
                LDSM_X4(bf[g][0], bf[g][1], bf[g][2], bf[g][3],
                        bbase + g * (16 * RSB) + ks * 32);
#pragma unroll
            for (int mt = 0; mt < 4; mt++)
#pragma unroll
                for (int nt = 0; nt < 4; nt++)
                    mma16816(acc[mt][nt], af[mt], bf[nt >> 1][(nt & 1) * 2],
                             bf[nt >> 1][(nt & 1) * 2 + 1]);
        }
        __syncthreads();
    }

    const int mode = QKV ? (n0 >> 10) : 3;   // 0=Q, 1=K, 2=V(transpose), 3=fp32 C
    if (mode == 2) {
        __half* sT = (__half*)dsm;
#pragma unroll
        for (int mt = 0; mt < 4; mt++) {
#pragma unroll
            for (int nt = 0; nt < 4; nt++) {
                const int cl = wn * 32 + nt * 8 + (l & 3) * 2;
                const int rl = wm * 64 + mt * 16 + (l >> 2);
#pragma unroll
                for (int rr = 0; rr < 2; rr++) {
                    sT[(size_t)cl * 136 + rl + rr * 8]       =
                        __float2half_rn(acc[mt][nt][rr * 2 + 0]);
                    sT[(size_t)(cl + 1) * 136 + rl + rr * 8] =
                        __float2half_rn(acc[mt][nt][rr * 2 + 1]);
                }
            }
        }
        __syncthreads();
        const int cl = tid & 127, half_ = tid >> 7;
        const int gcol = (n0 - 2048) + cl;
        const int hh = gcol >> 6, d = gcol & 63;
        const int token0 = m0 + half_ * 64;
        const int bb = token0 >> 11, t = token0 & 2047;
        const int kb = t >> 6;
        const size_t base = ((size_t)((bb * NH + hh) * NBLK + kb)) * TILE_H + (size_t)d * 72;
        const __half* src = sT + (size_t)cl * 136 + half_ * 64;
#pragma unroll
        for (int j8 = 0; j8 < 8; j8++)
            *(uint4*)(Va + base + j8 * 8) = *(const uint4*)(src + j8 * 8);
        return;
    }

#pragma unroll
    for (int mt = 0; mt < 4; mt++) {
#pragma unroll
        for (int nt = 0; nt < 4; nt++) {
            const int mr = m0 + wm * 64 + mt * 16 + (l >> 2);
            const int nc = n0 + wn * 32 + nt * 8 + (l & 3) * 2;
            if (mode == 3) {
                *(float2*)(C + (size_t)mr * DIM + nc) =
                    make_float2(acc[mt][nt][0], acc[mt][nt][1]);
                *(float2*)(C + (size_t)(mr + 8) * DIM + nc) =
                    make_float2(acc[mt][nt][2], acc[mt][nt][3]);
            } else {
                const int cl = nc & 1023;
                const int hh = cl >> 6, d = cl & 63;
                __half* dst = (mode == 0) ? Qa : Ka;
#pragma unroll
                for (int rr = 0; rr < 2; rr++) {
                    const int row = mr + rr * 8;
                    const int bb = row >> 11, t = row & 2047;
                    const size_t base = ((size_t)((bb * NH + hh) * NBLK + (t >> 6))) * TILE_H
                                      + (size_t)(t & 63) * 72;
                    *(uint32_t*)(dst + base + d) =
                        pack2h(__float2half_rn(acc[mt][nt][rr * 2 + 0]),
                               __float2half_rn(acc[mt][nt][rr * 2 + 1]));
                }
            }
        }
    }
}

// ---------------- triple-buffered tensor-core block-sparse flash attention ----------------
// All-hi fp16, K=64 both GEMMs. Q in registers (staged via K-buffer 2).
// K/V triple-buffered, prefetch distance 2, per-buffer parity = (it/3)&1.
__global__ void __launch_bounds__(128, 4)
attn_mma(const __half* __restrict__ Qa, const __half* __restrict__ Ka,
         const __half* __restrict__ Va, __half* __restrict__ Oc)
{
    extern __shared__ char sm[];
    const uint32_t sb = smem_u32(sm);
    const uint32_t oK = 0, oV = 3 * TILE;

    const int tid = threadIdx.x, wid = tid >> 5, l = tid & 31;
    const int qb = blockIdx.x, h = blockIdx.y, b = blockIdx.z;
    const size_t bh = (size_t)(b * NH + h);

    const uint32_t mbQ = sb + 6 * TILE;      // +0 Q, +8/+16/+24 stage 0/1/2
    if (tid == 0) {
        MBAR_INIT(mbQ, 1);
        MBAR_INIT(mbQ + 8, 1); MBAR_INIT(mbQ + 16, 1); MBAR_INIT(mbQ + 24, 1);
    }
    __syncthreads();

    uint32_t am = 0;
#pragma unroll
    for (int kb = 0; kb < NBLK; kb++)
        am |= (g_bm[qb * NBLK + kb] ? 1u : 0u) << kb;

    const char* Kbase = (const char*)Ka + bh * NBLK * (size_t)TILE;
    const char* Vbase = (const char*)Va + bh * NBLK * (size_t)TILE;

    uint32_t am_pf = am;                     // blocks not yet prefetched
    // prologue: Q -> K-buf2; prefetch first two allowed blocks into bufs 0,1
    if (tid == 0) {
        MBAR_EXPECT(mbQ, TILE);
        BULKCP(sb + oK + 2 * TILE, (const char*)Qa + (bh * NBLK + qb) * (size_t)TILE, TILE, mbQ);
    }
#pragma unroll
    for (int s = 0; s < 2; s++) {
        if (am_pf) {
            const int kb = __ffs(am_pf) - 1;
            am_pf &= am_pf - 1;
            if (tid == 0) {
                MBAR_EXPECT(mbQ + 8 + 8 * s, 2 * TILE);
                BULKCP(sb + oK + s * TILE, Kbase + (size_t)kb * TILE, TILE, mbQ + 8 + 8 * s);
                BULKCP(sb + oV + s * TILE, Vbase + (size_t)kb * TILE, TILE, mbQ + 8 + 8 * s);
            }
        }
    }

    const uint32_t a_off = (uint32_t)((l & 15) * TRS + (l >> 4) * 16);
    const uint32_t b_off = (uint32_t)(((l & 7) + ((l >> 4) & 1) * 8) * TRS + ((l >> 3) & 1) * 16);

    // Q fragments -> registers (staged in K-buf2)
    MBAR_WAIT(mbQ, 0);
    uint32_t qf[4][4];
    {
        const uint32_t aQ = sb + oK + 2 * TILE + (uint32_t)(wid * 16) * TRS + a_off;
#pragma unroll
        for (int ks = 0; ks < 4; ks++)
            LDSM_X4(qf[ks][0], qf[ks][1], qf[ks][2], qf[ks][3], aQ + ks * 32);
    }
    __syncthreads();                          // K-buf2 free for prefetch (iter 0 issues it)

    float o[8][4];
#pragma unroll
    for (int nt = 0; nt < 8; nt++)
#pragma unroll
        for (int q = 0; q < 4; q++) o[nt][q] = 0.f;
    float m0 = -INFINITY, m1 = -INFINITY, l0 = 0.f, l1 = 0.f;
    const float scale = 0.125f;

    int it = 0;
    while (am) {
        am &= am - 1;                        // consume current block
        const int buf = it % 3;

        // prefetch the next unprefetched block into buffer (it+2)%3
        if (am_pf && tid == 0) {
            const int kb2 = __ffs(am_pf) - 1;
            const int s2 = (it + 2) % 3;
            MBAR_EXPECT(mbQ + 8 + 8 * s2, 2 * TILE);
            BULKCP(sb + oK + s2 * TILE, Kbase + (size_t)kb2 * TILE, TILE, mbQ + 8 + 8 * s2);
            BULKCP(sb + oV + s2 * TILE, Vbase + (size_t)kb2 * TILE, TILE, mbQ + 8 + 8 * s2);
        }
        if (am_pf) am_pf &= am_pf - 1;

        MBAR_WAIT(mbQ + 8 + 8 * buf, (it / 3) & 1);

        const uint32_t bK = sb + oK + buf * TILE + b_off;
        const uint32_t bV = sb + oV + buf * TILE + b_off;

        // ---- S = Q K^T, K=64 ----
        float s[8][4];
#pragma unroll
        for (int nt = 0; nt < 8; nt++)
#pragma unroll
            for (int q = 0; q < 4; q++) s[nt][q] = 0.f;
#pragma unroll
        for (int ks = 0; ks < 4; ks++) {
            uint32_t bf[4][4];
#pragma unroll
            for (int g = 0; g < 4; g++)
                LDSM_X4(bf[g][0], bf[g][1], bf[g][2], bf[g][3],
                        bK + g * (16 * TRS) + ks * 32);
#pragma unroll
            for (int nt = 0; nt < 8; nt++)
                mma16816(s[nt], qf[ks], bf[nt >> 1][(nt & 1) * 2], bf[nt >> 1][(nt & 1) * 2 + 1]);
        }

        // ---- online softmax; P_hi fragments in registers ----
        float vm0 = -INFINITY, vm1 = -INFINITY;
#pragma unroll
        for (int nt = 0; nt < 8; nt++) {
#pragma unroll
            for (int q = 0; q < 4; q++) s[nt][q] *= scale;
            vm0 = fmaxf(vm0, fmaxf(s[nt][0], s[nt][1]));
            vm1 = fmaxf(vm1, fmaxf(s[nt][2], s[nt][3]));
        }
        vm0 = fmaxf(vm0, __shfl_xor_sync(0xffffffff, vm0, 1));
        vm0 = fmaxf(vm0, __shfl_xor_sync(0xffffffff, vm0, 2));
        vm1 = fmaxf(vm1, __shfl_xor_sync(0xffffffff, vm1, 1));
        vm1 = fmaxf(vm1, __shfl_xor_sync(0xffffffff, vm1, 2));

        const float mn0 = fmaxf(m0, vm0), mn1 = fmaxf(m1, vm1);
        const float al0 = __expf(m0 - mn0), al1 = __expf(m1 - mn1);
        m0 = mn0; m1 = mn1;

        uint32_t phi0[8], phi1[8];
        float rs0 = 0.f, rs1 = 0.f;
#pragma unroll
        for (int nt = 0; nt < 8; nt++) {
            float p00 = __expf(s[nt][0] - mn0), p01 = __expf(s[nt][1] - mn0);
            float p10 = __expf(s[nt][2] - mn1), p11 = __expf(s[nt][3] - mn1);
            rs0 += p00 + p01; rs1 += p10 + p11;
            phi0[nt] = pack2h(__float2half_rn(p00), __float2half_rn(p01));
            phi1[nt] = pack2h(__float2half_rn(p10), __float2half_rn(p11));
            o[nt][0] *= al0; o[nt][1] *= al0;
            o[nt][2] *= al1; o[nt][3] *= al1;
        }
        rs0 += __shfl_xor_sync(0xffffffff, rs0, 1);
        rs0 += __shfl_xor_sync(0xffffffff, rs0, 2);
        rs1 += __shfl_xor_sync(0xffffffff, rs1, 1);
        rs1 += __shfl_xor_sync(0xffffffff, rs1, 2);
        l0 = l0 * al0 + rs0;
        l1 = l1 * al1 + rs1;

        // ---- O += P_hi Vt^T, K=64 ----
#pragma unroll
        for (int ks = 0; ks < 4; ks++) {
            uint32_t af[4], bf[4][4];
            af[0] = phi0[2 * ks];     af[1] = phi1[2 * ks];
            af[2] = phi0[2 * ks + 1]; af[3] = phi1[2 * ks + 1];
#pragma unroll
            for (int g = 0; g < 4; g++)
                LDSM_X4(bf[g][0], bf[g][1], bf[g][2], bf[g][3],
                        bV + g * (16 * TRS) + ks * 32);
#pragma unroll
            for (int nt = 0; nt < 8; nt++)
                mma16816(o[nt], af, bf[nt >> 1][(nt & 1) * 2], bf[nt >> 1][(nt & 1) * 2 + 1]);
        }

        __syncthreads();                      // all warps done with this buffer
        it++;
    }

    // epilogue: write Oc in GEMM-tiled layout (hi only)
    const float inv0 = 1.f / l0, inv1 = 1.f / l1;
    const int r0 = qb * 64 + wid * 16 + (l >> 2);
    const int c0 = h * 64 + (l & 3) * 2;
#pragma unroll
    for (int nt = 0; nt < 8; nt++) {
        const int col = c0 + nt * 8;
#pragma unroll
        for (int rr = 0; rr < 2; rr++) {
            const float inv = rr ? inv1 : inv0;
            const int row = b * SEQ + r0 + rr * 8;
            const size_t idx = ((size_t)((row >> 7) * 16 + (col >> 6))) * STAGE_H
                             + (row & 127) * 72 + (col & 63);
            __half hx = __float2half_rn(o[nt][rr * 2 + 0] * inv);
            __half hy = __float2half_rn(o[nt][rr * 2 + 1] * inv);
            *(uint32_t*)(Oc + idx) = pack2h(hx, hy);
        }
    }
}

// ---------------- launcher ----------------
extern "C" void kernel_launch(void* const* d_in, const int* in_sizes, int n_in,
                              void* d_out, int out_size)
{
    const float* X  = (const float*)d_in[0];
    const float* Wq = (const float*)d_in[1];
    const float* Wk = (const float*)d_in[2];
    const float* Wv = (const float*)d_in[3];
    const float* Wo = (const float*)d_in[4];
    const unsigned char* mask = (const unsigned char*)d_in[5];
    float* out = (float*)d_out;

    __half *Xc, *Oc, *Wqkv, *Woc, *Qa, *Ka, *Va;
    cudaGetSymbolAddress((void**)&Xc, g_Xc);
    cudaGetSymbolAddress((void**)&Oc, g_Oc);
    cudaGetSymbolAddress((void**)&Wqkv, g_Wqkv);
    cudaGetSymbolAddress((void**)&Woc, g_Wo);
    cudaGetSymbolAddress((void**)&Qa, g_Qa);
    cudaGetSymbolAddress((void**)&Ka, g_Ka);
    cudaGetSymbolAddress((void**)&Va, g_Va);

    cudaFuncSetAttribute(gemm_mma<true>,  cudaFuncAttributeMaxDynamicSharedMemorySize, SM_TOTAL);
    cudaFuncSetAttribute(gemm_mma<false>, cudaFuncAttributeMaxDynamicSharedMemorySize, SM_TOTAL);
    cudaFuncSetAttribute(attn_mma, cudaFuncAttributeMaxDynamicSharedMemorySize, ASM_TOTAL);

    build_block_mask<<<1, 1024>>>(mask);                                          // 1
    conv_act<<<(MROWS * DIM + 255) / 256, 256>>>(X, Xc, MROWS);                   // 2
    conv_wgt_all<<<(4 * DIM * DIM + 255) / 256, 256>>>(Wq, Wk, Wv, Wo, Wqkv, Woc);// 3

    dim3 qkvgrid(3 * DIM / TN, MROWS / TM);   // (24, 32)
    gemm_mma<true><<<qkvgrid, 256, SM_TOTAL>>>(Xc, Wqkv, Qa, Ka, Va, nullptr);    // 4

    dim3 agrid(NBLK, NH, BATCH);
    attn_mma<<<agrid, 128, ASM_TOTAL>>>(Qa, Ka, Va, Oc);                          // 5

    dim3 ogrid(DIM / TN, MROWS / TM);         // (8, 32)
    gemm_mma<false><<<ogrid, 256, SM_TOTAL>>>(Oc, Woc, nullptr, nullptr, nullptr, out); // 6
}